// round 12
// baseline (speedup 1.0000x reference)
#include <cuda_runtime.h>
#include <cuda_bf16.h>
#include <cstdint>

#define N_NODES   4000000
#define N_GRAPHS  4096
#define D_FEAT    8
#define N_CLASSES 10
#define N_TICKETS (2 * N_GRAPHS)        // half-segment granularity
#define B_BLOCKS  1024
#define B_WARPS   4096
#define FULL 0xFFFFFFFFu

__device__ int   g_seg_start[N_GRAPHS + 1];
__device__ float g_sums[N_GRAPHS * D_FEAT];
__device__ int   g_done[N_GRAPHS];
__device__ int   g_ticket;

// batch_ids may be int64 OR int32 (JAX under default x64=False silently makes
// them int32). Values < 4096, so for int64 data every high word is 0: viewing
// the buffer as int32, element N_NODES-1 is an int64 high word (==0) or the
// max sorted int32 id (>0).
__device__ __forceinline__ int id_at(const int* __restrict__ ids32, bool is64, int i) {
    return is64 ? ids32[2 * i] : ids32[i];
}

// Half-warp cooperative 16-ary lower_bound of v over sorted ids in [lo, hi).
__device__ __forceinline__ int kary_lower_bound(
    const int* __restrict__ ids32, bool is64, int v,
    int lo, int hi, int sub, int half_shift)
{
    const unsigned hmask = 0xFFFFu << half_shift;
    while (hi - lo > 16) {
        const int range = hi - lo;
        const int pos = lo + (int)(((long long)range * (sub + 1)) >> 4);
        const bool less = id_at(ids32, is64, pos - 1) < v;
        const unsigned ball = __ballot_sync(hmask, less);
        const int cnt = __popc((ball >> half_shift) & 0xFFFFu);
        const int nlo = lo + (int)(((long long)range * cnt) >> 4);
        const int nhi = (cnt == 16) ? hi
                      : lo + (int)(((long long)range * (cnt + 1)) >> 4);
        lo = nlo; hi = nhi;
    }
    const int pos = lo + sub;
    const bool less = (pos < hi) ? (id_at(ids32, is64, pos) < v) : false;
    const unsigned ball = __ballot_sync(hmask, less);
    return lo + __popc((ball >> half_shift) & 0xFFFFu);
}

// ---- Kernel A: all 4097 boundaries + zero scratch + init ticket counter ----
// 512 blocks x 128 threads = 2048 warps; warp w resolves boundaries 2w, 2w+1.
__global__ __launch_bounds__(128) void bounds_kernel(const int* __restrict__ ids32) {
    const int tid  = blockIdx.x * 128 + threadIdx.x;
    if (tid < N_GRAPHS * D_FEAT) g_sums[tid] = 0.0f;
    if (tid < N_GRAPHS)          g_done[tid] = 0;
    if (tid == 0) { g_ticket = B_WARPS; g_seg_start[N_GRAPHS] = N_NODES; }

    const int wid  = tid >> 5;
    const int lane = threadIdx.x & 31;
    const int half_shift = lane & 16;
    const int sub = lane & 15;
    const int v = 2 * wid + (half_shift ? 1 : 0);   // 0..4095
    if (v >= N_GRAPHS) return;

    const bool is64 = (ids32[N_NODES - 1] == 0);
    const long long approx = ((long long)v * N_NODES) >> 12;
    int lo = (int)(approx - 8192); if (lo < 0) lo = 0;
    int hi = (int)(approx + 8192); if (hi > N_NODES) hi = N_NODES;
    const bool ok_lo = (lo == 0)       || (id_at(ids32, is64, lo - 1) < v);
    const bool ok_hi = (hi == N_NODES) || (id_at(ids32, is64, hi) >= v);
    if (!(ok_lo && ok_hi)) { lo = 0; hi = N_NODES; }
    const int res = kary_lower_bound(ids32, is64, v, lo, hi, sub, half_shift);
    if ((lane & 15) == 0) g_seg_start[v] = res;
}

// ---- Kernel B: work-stealing stream + inline last-half finalize ------------
__global__ __launch_bounds__(128) void stream_kernel(
    const float4* __restrict__ x4,
    const float*  __restrict__ W,      // [10, 8]
    const float*  __restrict__ b,      // [10]
    float*        __restrict__ out)    // [4096, 10]
{
    const int lane = threadIdx.x & 31;
    int t = (blockIdx.x * 128 + threadIdx.x) >> 5;   // static first ticket

    while (t < N_TICKETS) {
        const int g = t >> 1;
        const int h = t & 1;
        const int s = __ldg(&g_seg_start[g]);
        const int e = __ldg(&g_seg_start[g + 1]);
        const int cnt = e - s;
        const int n4  = cnt * 2;
        const int h4  = (n4 >> 1) & ~1;              // even split point
        const int b0  = h ? h4 : 0;
        const int b1  = h ? n4 : h4;
        const long long base = (long long)s * 2 + b0;
        const int len = b1 - b0;                      // even

        // ---- stream this half-segment (evict-first, unroll 8) ----
        float4 a0 = make_float4(0.f,0.f,0.f,0.f);
        float4 a1 = make_float4(0.f,0.f,0.f,0.f);
        float4 a2 = make_float4(0.f,0.f,0.f,0.f);
        float4 a3 = make_float4(0.f,0.f,0.f,0.f);
        int c = 0;
        while (c + 256 <= len) {
            const long long p = base + c + lane;
            float4 v0 = __ldcs(&x4[p      ]);
            float4 v1 = __ldcs(&x4[p +  32]);
            float4 v2 = __ldcs(&x4[p +  64]);
            float4 v3 = __ldcs(&x4[p +  96]);
            float4 v4 = __ldcs(&x4[p + 128]);
            float4 v5 = __ldcs(&x4[p + 160]);
            float4 v6 = __ldcs(&x4[p + 192]);
            float4 v7 = __ldcs(&x4[p + 224]);
            a0.x += v0.x; a0.y += v0.y; a0.z += v0.z; a0.w += v0.w;
            a1.x += v1.x; a1.y += v1.y; a1.z += v1.z; a1.w += v1.w;
            a2.x += v2.x; a2.y += v2.y; a2.z += v2.z; a2.w += v2.w;
            a3.x += v3.x; a3.y += v3.y; a3.z += v3.z; a3.w += v3.w;
            a0.x += v4.x; a0.y += v4.y; a0.z += v4.z; a0.w += v4.w;
            a1.x += v5.x; a1.y += v5.y; a1.z += v5.z; a1.w += v5.w;
            a2.x += v6.x; a2.y += v6.y; a2.z += v6.z; a2.w += v6.w;
            a3.x += v7.x; a3.y += v7.y; a3.z += v7.z; a3.w += v7.w;
            c += 256;
        }
        for (int j = c + lane; j < len; j += 32) {
            float4 vv = __ldcs(&x4[base + j]);
            a0.x += vv.x; a0.y += vv.y; a0.z += vv.z; a0.w += vv.w;
        }
        a0.x += a1.x + a2.x + a3.x;
        a0.y += a1.y + a2.y + a3.y;
        a0.z += a1.z + a2.z + a3.z;
        a0.w += a1.w + a2.w + a3.w;

        // Parity butterfly (base even -> lane parity == float4 parity):
        // lane 0 -> cols 0-3, lane 1 -> cols 4-7.
        #pragma unroll
        for (int m = 16; m >= 2; m >>= 1) {
            a0.x += __shfl_xor_sync(FULL, a0.x, m);
            a0.y += __shfl_xor_sync(FULL, a0.y, m);
            a0.z += __shfl_xor_sync(FULL, a0.z, m);
            a0.w += __shfl_xor_sync(FULL, a0.w, m);
        }
        // redistribute: lane d (0..7) gets column d
        const int  src = lane >> 2;
        const float vx = __shfl_sync(FULL, a0.x, src);
        const float vy = __shfl_sync(FULL, a0.y, src);
        const float vz = __shfl_sync(FULL, a0.z, src);
        const float vw = __shfl_sync(FULL, a0.w, src);
        if (lane < D_FEAT) {
            const float val = (lane & 2) ? ((lane & 1) ? vw : vz)
                                         : ((lane & 1) ? vy : vx);
            atomicAdd(&g_sums[g * D_FEAT + lane], val);
        }
        __syncwarp(FULL);
        __threadfence();

        int old = 0;
        if (lane == 0) old = atomicAdd(&g_done[g], 1);
        old = __shfl_sync(FULL, old, 0);

        if (old == 1) {   // both halves done: this warp finalizes segment g
            __threadfence();
            float sv = 0.0f;
            if (lane < D_FEAT) sv = __ldcg(&g_sums[g * D_FEAT + lane]);
            const float inv = (cnt > 0) ? (1.0f / (float)cnt) : 0.0f;
            const float p0 = __shfl_sync(FULL, sv, 0) * inv;
            const float p1 = __shfl_sync(FULL, sv, 1) * inv;
            const float p2 = __shfl_sync(FULL, sv, 2) * inv;
            const float p3 = __shfl_sync(FULL, sv, 3) * inv;
            const float p4 = __shfl_sync(FULL, sv, 4) * inv;
            const float p5 = __shfl_sync(FULL, sv, 5) * inv;
            const float p6 = __shfl_sync(FULL, sv, 6) * inv;
            const float p7 = __shfl_sync(FULL, sv, 7) * inv;
            if (lane < N_CLASSES) {
                const float* w = W + lane * D_FEAT;
                float r = __ldg(&b[lane]);
                r += p0 * __ldg(&w[0]) + p1 * __ldg(&w[1])
                   + p2 * __ldg(&w[2]) + p3 * __ldg(&w[3]);
                r += p4 * __ldg(&w[4]) + p5 * __ldg(&w[5])
                   + p6 * __ldg(&w[6]) + p7 * __ldg(&w[7]);
                out[g * N_CLASSES + lane] = r;
            }
        }

        // ---- steal next ticket ----
        if (lane == 0) t = atomicAdd(&g_ticket, 1);
        t = __shfl_sync(FULL, t, 0);
    }
}

extern "C" void kernel_launch(void* const* d_in, const int* in_sizes, int n_in,
                              void* d_out, int out_size) {
    // Bind inputs by element count (robust to metadata ordering):
    //   x: 32,000,000 f32 | batch_ids: 4,000,000 | W: 80 | b: 10
    const float* x   = nullptr;
    const void*  ids = nullptr;
    const float* W   = nullptr;
    const float* b   = nullptr;
    for (int i = 0; i < n_in; i++) {
        switch (in_sizes[i]) {
            case N_NODES * D_FEAT:   x   = (const float*)d_in[i]; break;
            case N_NODES:            ids = d_in[i];               break;
            case N_CLASSES * D_FEAT: W   = (const float*)d_in[i]; break;
            case N_CLASSES:          b   = (const float*)d_in[i]; break;
            default: break; // input_ids / attention_mask: unused
        }
    }
    float* out = (float*)d_out;

    bounds_kernel<<<512, 128>>>((const int*)ids);
    stream_kernel<<<B_BLOCKS, 128>>>((const float4*)x, W, b, out);
}